// round 2
// baseline (speedup 1.0000x reference)
#include <cuda_runtime.h>
#include <cstdint>
#include <cstddef>

// Problem constants
#define BB   2
#define LL   8192
#define SSEQ 4096
#define DD   1024
#define NH   16
#define NKV  4
#define HD   64
#define BS   16
#define NBLK (LL/BS)      // 512 query blocks per batch
#define HPG  (NH/NKV)     // 4 heads per kv group
#define QR   (BB*NBLK)    // 1024 pooled rows
#define KR   (BB*SSEQ)    // 8192 kv rows
#define QK_SCALE 0.125f   // 1/sqrt(64)

// Scratch (static device globals; no allocation allowed)
__device__ float g_pooled[QR*DD];      // [B*nb, D]
__device__ float g_q[QR*NH*HD];        // [B*nb, H*HD]
__device__ float g_k[KR*NKV*HD];       // [B*S, HKV*HD]
__device__ float g_v[KR*NKV*HD];       // [B*S, HKV*HD]
__device__ float g_o[QR*NH*HD];        // [B*nb, H*HD]

// ---------------------------------------------------------------------------
// Kernel 1: block-mean pooling.  One CTA per (b, qb) row; 256 thr x float4.
// ---------------------------------------------------------------------------
__global__ __launch_bounds__(256) void pool_kernel(const float* __restrict__ x) {
    const int row = blockIdx.x;            // b*NBLK + qb  (x is [B,L,D] contiguous)
    const int d   = threadIdx.x * 4;
    const float* xp = x + (size_t)row * (BS * DD) + d;
    float4 acc = make_float4(0.f, 0.f, 0.f, 0.f);
#pragma unroll
    for (int t = 0; t < BS; t++) {
        float4 v = __ldg((const float4*)(xp + (size_t)t * DD));
        acc.x += v.x; acc.y += v.y; acc.z += v.z; acc.w += v.w;
    }
    const float inv = 1.0f / BS;
    acc.x *= inv; acc.y *= inv; acc.z *= inv; acc.w *= inv;
    *(float4*)(g_pooled + (size_t)row * DD + d) = acc;
}

// ---------------------------------------------------------------------------
// Kernel 2: classic 128x128x8 SGEMM, 256 threads, 8x8 microtile.
// A[M,K] @ B[K,N] -> C[M,N], all row-major, M%128==0, N%128==0, K%8==0.
// BCAST: epilogue broadcasts each C row to 16 consecutive output token rows.
// ---------------------------------------------------------------------------
template<bool BCAST>
__global__ __launch_bounds__(256) void sgemm_kernel(
    const float* __restrict__ A, const float* __restrict__ B,
    float* __restrict__ C, int M, int N, int K)
{
    __shared__ float As[8][128];   // As[k][m] (transposed on load)
    __shared__ float Bs[8][128];   // Bs[k][n]

    const int tid = threadIdx.x;
    const int tx = tid & 15, ty = tid >> 4;
    const int m0 = blockIdx.y * 128, n0 = blockIdx.x * 128;

    const int arow = tid >> 1;          // 0..127
    const int akp  = (tid & 1) * 4;     // 0 or 4
    const int brow = tid >> 5;          // 0..7
    const int bcol = (tid & 31) * 4;    // 0..124

    const float* Ap = A + (size_t)(m0 + arow) * K + akp;
    const float* Bp = B + (size_t)brow * N + n0 + bcol;

    float acc[8][8];
#pragma unroll
    for (int i = 0; i < 8; i++)
#pragma unroll
        for (int j = 0; j < 8; j++) acc[i][j] = 0.f;

    for (int k0 = 0; k0 < K; k0 += 8) {
        float4 av = __ldg((const float4*)(Ap + k0));
        float4 bv = __ldg((const float4*)(Bp + (size_t)k0 * N));
        As[akp + 0][arow] = av.x;
        As[akp + 1][arow] = av.y;
        As[akp + 2][arow] = av.z;
        As[akp + 3][arow] = av.w;
        *(float4*)&Bs[brow][bcol] = bv;
        __syncthreads();
#pragma unroll
        for (int k = 0; k < 8; k++) {
            float4 a0 = *(const float4*)&As[k][ty * 8];
            float4 a1 = *(const float4*)&As[k][ty * 8 + 4];
            float4 b0 = *(const float4*)&Bs[k][tx * 8];
            float4 b1 = *(const float4*)&Bs[k][tx * 8 + 4];
            float ar[8] = {a0.x, a0.y, a0.z, a0.w, a1.x, a1.y, a1.z, a1.w};
            float br[8] = {b0.x, b0.y, b0.z, b0.w, b1.x, b1.y, b1.z, b1.w};
#pragma unroll
            for (int i = 0; i < 8; i++)
#pragma unroll
                for (int j = 0; j < 8; j++)
                    acc[i][j] = fmaf(ar[i], br[j], acc[i][j]);
        }
        __syncthreads();
    }

    if (!BCAST) {
#pragma unroll
        for (int i = 0; i < 8; i++) {
            float* cp = C + (size_t)(m0 + ty * 8 + i) * N + n0 + tx * 8;
            *(float4*)(cp)     = make_float4(acc[i][0], acc[i][1], acc[i][2], acc[i][3]);
            *(float4*)(cp + 4) = make_float4(acc[i][4], acc[i][5], acc[i][6], acc[i][7]);
        }
    } else {
        // rows are (b*NBLK + qb); each block row fans out to BS token rows of out[B,L,D]
#pragma unroll
        for (int i = 0; i < 8; i++) {
            const int row = m0 + ty * 8 + i;
            const int b  = row >> 9;           // /NBLK
            const int qb = row & (NBLK - 1);
            float* cp = C + ((size_t)b * LL + (size_t)qb * BS) * DD + n0 + tx * 8;
            float4 v0 = make_float4(acc[i][0], acc[i][1], acc[i][2], acc[i][3]);
            float4 v1 = make_float4(acc[i][4], acc[i][5], acc[i][6], acc[i][7]);
#pragma unroll
            for (int t = 0; t < BS; t++) {
                *(float4*)(cp)     = v0;
                *(float4*)(cp + 4) = v1;
                cp += DD;
            }
        }
    }
}

// ---------------------------------------------------------------------------
// Kernel 3: fused masked flash attention (fp32).
// Grid: (nb/64, H, B).  CTA = 64 query blocks x 1 head, streams S in 64-chunks.
// 256 threads: tx = s/d columns (16), ty = q rows (16), 4x4 microtile.
// smem (dynamic, 66048 B): sQ[d][q] 64x64, sK[d][s] 64x64, sV[s][d] 64x64,
//                          sP[s*65+q], sM[64]
// ---------------------------------------------------------------------------
#define ATTN_SMEM ((64*64*3 + 64*65) * 4 + 64 * 4)

__global__ __launch_bounds__(256) void attn_kernel(const int* __restrict__ mask) {
    extern __shared__ float sm[];
    float* sQ = sm;                  // [d][q], pre-scaled
    float* sK = sm + 64 * 64;        // [d][s]
    float* sV = sm + 2 * 64 * 64;    // [s][d]
    float* sP = sm + 3 * 64 * 64;    // [s][q], pitch 65
    int*   sM = (int*)(sm + 3 * 64 * 64 + 64 * 65);

    const int tid = threadIdx.x;
    const int tx = tid & 15, ty = tid >> 4;
    const int h = blockIdx.y;
    const int g = h >> 2;            // kv group = h / HPG
    const int b = blockIdx.z;
    const int qb0 = blockIdx.x * 64;

    // Load Q tile transposed + pre-scaled: sQ[d][r]
    {
        const int lr = tid >> 2;            // q row 0..63
        const int c  = (tid & 3) * 16;      // d base
        const float* qp = g_q + (size_t)(b * NBLK + qb0 + lr) * (NH * HD) + h * HD + c;
#pragma unroll
        for (int u = 0; u < 4; u++) {
            float4 v = *(const float4*)(qp + u * 4);
            const int d = c + u * 4;
            sQ[(d + 0) * 64 + lr] = v.x * QK_SCALE;
            sQ[(d + 1) * 64 + lr] = v.y * QK_SCALE;
            sQ[(d + 2) * 64 + lr] = v.z * QK_SCALE;
            sQ[(d + 3) * 64 + lr] = v.w * QK_SCALE;
        }
    }

    float m_[4], l_[4], oacc[4][4];
#pragma unroll
    for (int i = 0; i < 4; i++) {
        m_[i] = -1e30f; l_[i] = 0.f;
#pragma unroll
        for (int j = 0; j < 4; j++) oacc[i][j] = 0.f;
    }

    for (int sc = 0; sc < SSEQ; sc += 64) {
        // Load K chunk (transposed) and V chunk (direct)
        {
            const int lr = tid >> 2;
            const int c  = (tid & 3) * 16;
            const float* kp = g_k + (size_t)(b * SSEQ + sc + lr) * (NKV * HD) + g * HD + c;
            const float* vp = g_v + (size_t)(b * SSEQ + sc + lr) * (NKV * HD) + g * HD + c;
#pragma unroll
            for (int u = 0; u < 4; u++) {
                float4 kv = *(const float4*)(kp + u * 4);
                const int d = c + u * 4;
                sK[(d + 0) * 64 + lr] = kv.x;
                sK[(d + 1) * 64 + lr] = kv.y;
                sK[(d + 2) * 64 + lr] = kv.z;
                sK[(d + 3) * 64 + lr] = kv.w;
                *(float4*)&sV[lr * 64 + c + u * 4] = *(const float4*)(vp + u * 4);
            }
        }
        if (tid < 64) sM[tid] = __ldg(mask + (size_t)b * SSEQ + sc + tid);
        __syncthreads();

        // S = (Q*scale) K^T : 4x4 microtile over inner d=64
        float sacc[4][4];
#pragma unroll
        for (int i = 0; i < 4; i++)
#pragma unroll
            for (int j = 0; j < 4; j++) sacc[i][j] = 0.f;
#pragma unroll 8
        for (int kk = 0; kk < 64; kk++) {
            float4 aq = *(const float4*)&sQ[kk * 64 + ty * 4];
            float4 bk = *(const float4*)&sK[kk * 64 + tx * 4];
            float ar[4] = {aq.x, aq.y, aq.z, aq.w};
            float br[4] = {bk.x, bk.y, bk.z, bk.w};
#pragma unroll
            for (int i = 0; i < 4; i++)
#pragma unroll
                for (int j = 0; j < 4; j++)
                    sacc[i][j] = fmaf(ar[i], br[j], sacc[i][j]);
        }

        // Mask + online softmax update
        int vm[4];
#pragma unroll
        for (int j = 0; j < 4; j++) vm[j] = sM[tx * 4 + j];
#pragma unroll
        for (int i = 0; i < 4; i++)
#pragma unroll
            for (int j = 0; j < 4; j++)
                if (!vm[j]) sacc[i][j] = -1e30f;

#pragma unroll
        for (int i = 0; i < 4; i++) {
            float mx = fmaxf(fmaxf(sacc[i][0], sacc[i][1]), fmaxf(sacc[i][2], sacc[i][3]));
#pragma unroll
            for (int off = 1; off < 16; off <<= 1)
                mx = fmaxf(mx, __shfl_xor_sync(0xffffffffu, mx, off));
            const float mn  = fmaxf(m_[i], mx);
            const float fac = __expf(m_[i] - mn);
            m_[i] = mn;
            float p[4];
#pragma unroll
            for (int j = 0; j < 4; j++)
                p[j] = vm[j] ? __expf(sacc[i][j] - mn) : 0.f;   // guard: all-masked chunk must give p=0
            float rs = p[0] + p[1] + p[2] + p[3];
#pragma unroll
            for (int off = 1; off < 16; off <<= 1)
                rs += __shfl_xor_sync(0xffffffffu, rs, off);
            l_[i] = l_[i] * fac + rs;
#pragma unroll
            for (int j = 0; j < 4; j++) oacc[i][j] *= fac;
#pragma unroll
            for (int j = 0; j < 4; j++)
                sP[(tx * 4 + j) * 65 + ty * 4 + i] = p[j];
        }
        __syncthreads();

        // O += P V : inner s=64, thread owns 4q x 4d
#pragma unroll 8
        for (int kk = 0; kk < 64; kk++) {
            float a0 = sP[kk * 65 + ty * 4 + 0];
            float a1 = sP[kk * 65 + ty * 4 + 1];
            float a2 = sP[kk * 65 + ty * 4 + 2];
            float a3 = sP[kk * 65 + ty * 4 + 3];
            float4 bv = *(const float4*)&sV[kk * 64 + tx * 4];
            oacc[0][0] = fmaf(a0, bv.x, oacc[0][0]); oacc[0][1] = fmaf(a0, bv.y, oacc[0][1]);
            oacc[0][2] = fmaf(a0, bv.z, oacc[0][2]); oacc[0][3] = fmaf(a0, bv.w, oacc[0][3]);
            oacc[1][0] = fmaf(a1, bv.x, oacc[1][0]); oacc[1][1] = fmaf(a1, bv.y, oacc[1][1]);
            oacc[1][2] = fmaf(a1, bv.z, oacc[1][2]); oacc[1][3] = fmaf(a1, bv.w, oacc[1][3]);
            oacc[2][0] = fmaf(a2, bv.x, oacc[2][0]); oacc[2][1] = fmaf(a2, bv.y, oacc[2][1]);
            oacc[2][2] = fmaf(a2, bv.z, oacc[2][2]); oacc[2][3] = fmaf(a2, bv.w, oacc[2][3]);
            oacc[3][0] = fmaf(a3, bv.x, oacc[3][0]); oacc[3][1] = fmaf(a3, bv.y, oacc[3][1]);
            oacc[3][2] = fmaf(a3, bv.z, oacc[3][2]); oacc[3][3] = fmaf(a3, bv.w, oacc[3][3]);
        }
        __syncthreads();
    }

    // Normalize + store
#pragma unroll
    for (int i = 0; i < 4; i++) {
        const float inv = 1.0f / l_[i];
        const int row = b * NBLK + qb0 + ty * 4 + i;
        float4 st = make_float4(oacc[i][0] * inv, oacc[i][1] * inv,
                                oacc[i][2] * inv, oacc[i][3] * inv);
        *(float4*)(g_o + (size_t)row * (NH * HD) + h * HD + tx * 4) = st;
    }
}

// ---------------------------------------------------------------------------
// Launch
// ---------------------------------------------------------------------------
extern "C" void kernel_launch(void* const* d_in, const int* in_sizes, int n_in,
                              void* d_out, int out_size) {
    (void)in_sizes; (void)n_in; (void)out_size;
    const float* x    = (const float*)d_in[0];
    const float* enc  = (const float*)d_in[1];
    const int*   mask = (const int*)  d_in[2];
    const float* Wq   = (const float*)d_in[3];
    const float* Wk   = (const float*)d_in[4];
    const float* Wv   = (const float*)d_in[5];
    const float* Wo   = (const float*)d_in[6];
    float* out = (float*)d_out;

    float *pPooled, *pQ, *pK, *pV, *pO;
    cudaGetSymbolAddress((void**)&pPooled, g_pooled);
    cudaGetSymbolAddress((void**)&pQ, g_q);
    cudaGetSymbolAddress((void**)&pK, g_k);
    cudaGetSymbolAddress((void**)&pV, g_v);
    cudaGetSymbolAddress((void**)&pO, g_o);

    // 1. pool decoder tokens into blocks
    pool_kernel<<<QR, 256>>>(x);

    // 2. projections
    sgemm_kernel<false><<<dim3((NH * HD) / 128, QR / 128), 256>>>(pPooled, Wq, pQ, QR, NH * HD, DD);
    sgemm_kernel<false><<<dim3((NKV * HD) / 128, KR / 128), 256>>>(enc, Wk, pK, KR, NKV * HD, DD);
    sgemm_kernel<false><<<dim3((NKV * HD) / 128, KR / 128), 256>>>(enc, Wv, pV, KR, NKV * HD, DD);

    // 3. fused masked attention over blocks
    cudaFuncSetAttribute(attn_kernel, cudaFuncAttributeMaxDynamicSharedMemorySize, ATTN_SMEM);
    attn_kernel<<<dim3(NBLK / 64, NH, BB), 256, ATTN_SMEM>>>(mask);

    // 4. output projection on block level, broadcast 16x into [B, L, D]
    sgemm_kernel<true><<<dim3(DD / 128, QR / 128), 256>>>(pO, Wo, out, QR, DD, NH * HD);
}